// round 1
// baseline (speedup 1.0000x reference)
#include <cuda_runtime.h>
#include <math.h>

#define BB 128
#define SS 512
#define EE 512
#define HH 512
#define NQ 8
#define TTAG 50
#define G4H 2048

// Scratch (device globals are the sanctioned scratch mechanism)
__device__ float g_Xz[(size_t)SS * BB * G4H];   // [t][b][4H] precomputed x@Wih^T + bias (536 MB)
__device__ float g_h[2][BB * HH];               // double-buffered hidden state
__device__ float g_c[BB * HH];                  // cell state (in-place, uniquely owned)

__device__ __forceinline__ float sigf(float x) {
    return 1.0f / (1.0f + __expf(-x));
}
__device__ __forceinline__ float tanhf_fast(float x) {
    // 1 - 2/(e^{2x}+1); exact limits at +-inf, ~1e-6 rel err
    return 1.0f - 2.0f / (__expf(2.0f * x) + 1.0f);
}

// ---------------------------------------------------------------------------
// Zero h0 and c0
// ---------------------------------------------------------------------------
__global__ void init_kernel() {
    int i = blockIdx.x * blockDim.x + threadIdx.x;
    const int n = BB * HH;
    for (; i < n; i += gridDim.x * blockDim.x) {
        g_h[0][i] = 0.0f;
        g_c[i] = 0.0f;
    }
}

// ---------------------------------------------------------------------------
// Precompute g_Xz[t][b][col] = sum_e x[b][t][e] * Wih[col][e] + bih[col]+bhh[col]
// Tile: BM=128 (one timestep t per m-block, rows = batch), BN=64, BK=16.
// 256 threads, each computes an 8x4 micro-tile.
// ---------------------------------------------------------------------------
__global__ __launch_bounds__(256) void precompute_kernel(
    const float* __restrict__ x, const float* __restrict__ Wih,
    const float* __restrict__ bih, const float* __restrict__ bhh)
{
    __shared__ float As[16][132];   // [k][m], padded
    __shared__ float Bs[16][68];    // [k][n], padded

    const int t   = blockIdx.y;        // timestep == m-block (m0 = t*128)
    const int n0  = blockIdx.x * 64;
    const int tid = threadIdx.x;

    const int tym = tid >> 4;          // 0..15 -> 8 rows each
    const int txn = tid & 15;          // 0..15 -> 4 cols each

    float acc[8][4];
#pragma unroll
    for (int i = 0; i < 8; i++)
#pragma unroll
        for (int j = 0; j < 4; j++) acc[i][j] = 0.0f;

    // loader indices
    const int la_b = tid >> 1;               // batch row 0..127
    const int la_k = (tid & 1) * 8;          // 0 or 8
    const float* xrow = x + ((size_t)la_b * SS + t) * EE;
    const int lb_c = tid >> 2;               // 0..63
    const int lb_k = (tid & 3) * 4;
    const float* wrow = Wih + (size_t)(n0 + lb_c) * EE;

    for (int kc = 0; kc < EE; kc += 16) {
        float4 a0 = *(const float4*)(xrow + kc + la_k);
        float4 a1 = *(const float4*)(xrow + kc + la_k + 4);
        float4 b0 = *(const float4*)(wrow + kc + lb_k);
        As[la_k + 0][la_b] = a0.x;
        As[la_k + 1][la_b] = a0.y;
        As[la_k + 2][la_b] = a0.z;
        As[la_k + 3][la_b] = a0.w;
        As[la_k + 4][la_b] = a1.x;
        As[la_k + 5][la_b] = a1.y;
        As[la_k + 6][la_b] = a1.z;
        As[la_k + 7][la_b] = a1.w;
        Bs[lb_k + 0][lb_c] = b0.x;
        Bs[lb_k + 1][lb_c] = b0.y;
        Bs[lb_k + 2][lb_c] = b0.z;
        Bs[lb_k + 3][lb_c] = b0.w;
        __syncthreads();

#pragma unroll
        for (int k = 0; k < 16; k++) {
            float4 a04 = *(const float4*)&As[k][tym * 8];
            float4 a14 = *(const float4*)&As[k][tym * 8 + 4];
            float4 b4  = *(const float4*)&Bs[k][txn * 4];
            float av[8] = {a04.x, a04.y, a04.z, a04.w, a14.x, a14.y, a14.z, a14.w};
            float bv[4] = {b4.x, b4.y, b4.z, b4.w};
#pragma unroll
            for (int i = 0; i < 8; i++)
#pragma unroll
                for (int j = 0; j < 4; j++)
                    acc[i][j] = fmaf(av[i], bv[j], acc[i][j]);
        }
        __syncthreads();
    }

    // epilogue: add (bih+bhh), write to g_Xz
    const int col = n0 + txn * 4;
    float4 bi4 = *(const float4*)(bih + col);
    float4 bh4 = *(const float4*)(bhh + col);
    float bias[4] = {bi4.x + bh4.x, bi4.y + bh4.y, bi4.z + bh4.z, bi4.w + bh4.w};
#pragma unroll
    for (int i = 0; i < 8; i++) {
        const int b = tym * 8 + i;                 // batch row within tile
        float4 o;
        o.x = acc[i][0] + bias[0];
        o.y = acc[i][1] + bias[1];
        o.z = acc[i][2] + bias[2];
        o.w = acc[i][3] + bias[3];
        *(float4*)(g_Xz + ((size_t)t * BB + b) * G4H + col) = o;
    }
}

// ---------------------------------------------------------------------------
// One LSTM timestep, fused: z = Xz[t] + h_{t-1} @ Whh^T, then gate math.
// 128 CTAs; CTA owns hidden units j0..j0+3 (16 pre-activation columns:
// 4 j x 4 gates), all 128 batch rows. 256 threads: warp w -> batch rows
// [16w,16w+16); half-warp ch=0 computes gates (i,f), ch=1 computes (g,o);
// shfl_xor(16) exchanges so ch=0 performs the c/h update.
// ---------------------------------------------------------------------------
__global__ __launch_bounds__(256) void step_kernel(const float* __restrict__ Whh, int t)
{
    __shared__ float hs[128][36];   // h chunk [b][k], padded (stride 144B)
    __shared__ float Ws[16][36];    // Whh rows for our 16 cols, k chunk

    const float* __restrict__ hprev = g_h[t & 1];
    float* __restrict__ hnext = g_h[(t + 1) & 1];

    const int j0  = blockIdx.x * 4;
    const int tid = threadIdx.x;
    const int w   = tid >> 5;
    const int l   = tid & 31;
    const int b   = (w << 4) | (l & 15);   // batch row for this thread
    const int ch  = l >> 4;                // 0: gates i,f ; 1: gates g,o

    // loader indices
    const int lh_r = tid >> 1;             // 0..127
    const int lh_k = (tid & 1) * 16;
    const int lw_c = tid >> 4;             // 0..15 (col index: gate*4 + jj)
    const int lw_g = lw_c >> 2;
    const int lw_j = lw_c & 3;
    const float* wrow = Whh + (size_t)(lw_g * HH + j0 + lw_j) * HH;
    const int lw_k = (tid & 15) * 2;

    float acc[8] = {0.f, 0.f, 0.f, 0.f, 0.f, 0.f, 0.f, 0.f};

    for (int kc = 0; kc < HH; kc += 32) {
        const float4* hsrc = (const float4*)(hprev + (size_t)lh_r * HH + kc + lh_k);
        float4 h0 = hsrc[0], h1 = hsrc[1], h2 = hsrc[2], h3 = hsrc[3];
        *(float4*)&hs[lh_r][lh_k + 0]  = h0;
        *(float4*)&hs[lh_r][lh_k + 4]  = h1;
        *(float4*)&hs[lh_r][lh_k + 8]  = h2;
        *(float4*)&hs[lh_r][lh_k + 12] = h3;
        float2 wv = *(const float2*)(wrow + kc + lw_k);
        *(float2*)&Ws[lw_c][lw_k] = wv;
        __syncthreads();

#pragma unroll
        for (int k = 0; k < 32; k += 4) {
            float4 h4 = *(const float4*)&hs[b][k];
#pragma unroll
            for (int cc = 0; cc < 8; cc++) {
                float4 w4 = *(const float4*)&Ws[ch * 8 + cc][k];
                acc[cc] = fmaf(h4.x, w4.x, acc[cc]);
                acc[cc] = fmaf(h4.y, w4.y, acc[cc]);
                acc[cc] = fmaf(h4.z, w4.z, acc[cc]);
                acc[cc] = fmaf(h4.w, w4.w, acc[cc]);
            }
        }
        __syncthreads();
    }

    // add precomputed x-part (+bias). ch=0: gates 0(i),1(f); ch=1: gates 2(g),3(o)
    const float* xz = g_Xz + ((size_t)t * BB + b) * G4H;
    float4 xa = *(const float4*)(xz + (ch * 2 + 0) * HH + j0);
    float4 xb = *(const float4*)(xz + (ch * 2 + 1) * HH + j0);
    acc[0] += xa.x; acc[1] += xa.y; acc[2] += xa.z; acc[3] += xa.w;
    acc[4] += xb.x; acc[5] += xb.y; acc[6] += xb.z; acc[7] += xb.w;

    float oth[8];
#pragma unroll
    for (int q = 0; q < 8; q++) oth[q] = __shfl_xor_sync(0xffffffffu, acc[q], 16);

    if (ch == 0) {
        float4 c4 = *(const float4*)&g_c[(size_t)b * HH + j0];
        float co[4] = {c4.x, c4.y, c4.z, c4.w};
        float cn[4], hn[4];
#pragma unroll
        for (int jj = 0; jj < 4; jj++) {
            float zi = acc[jj], zf = acc[4 + jj];
            float zg = oth[jj], zo = oth[4 + jj];
            float cv = sigf(zf) * co[jj] + sigf(zi) * tanhf_fast(zg);
            cn[jj] = cv;
            hn[jj] = sigf(zo) * tanhf_fast(cv);
        }
        *(float4*)&g_c[(size_t)b * HH + j0]   = make_float4(cn[0], cn[1], cn[2], cn[3]);
        *(float4*)&hnext[(size_t)b * HH + j0] = make_float4(hn[0], hn[1], hn[2], hn[3]);
    }
}

// ---------------------------------------------------------------------------
// Quantum head + log_softmax. One CTA per batch row, 128 threads.
// Reference: f=sig(cos(hx@Wf^T+bf+thf)); g=tanh(cos(hx@Wu^T+bu+thu));
//            o=sig(cos(hx@Wo^T+bo+tho)); h_out=o*tanh(f*g);
//            out = log_softmax(h_out@Wt^T + bt)      ("i" path unused)
// ---------------------------------------------------------------------------
__global__ __launch_bounds__(128) void final_kernel(
    const float* __restrict__ Wf, const float* __restrict__ bf,
    const float* __restrict__ Wu, const float* __restrict__ bu,
    const float* __restrict__ Wo, const float* __restrict__ bo,
    const float* __restrict__ thf, const float* __restrict__ thu,
    const float* __restrict__ tho,
    const float* __restrict__ Wt, const float* __restrict__ bt,
    float* __restrict__ out)
{
    __shared__ float sx[HH];
    __shared__ float q[3][NQ];
    __shared__ float hout[NQ];
    __shared__ float lg[TTAG];
    __shared__ float lse;

    const int b = blockIdx.x;
    const int tid = threadIdx.x;
    const float* hx = g_h[0] + (size_t)b * HH;   // (511+1)&1 == 0 -> final h in buf 0

    for (int k = tid; k < HH; k += 128) sx[k] = hx[k];
    __syncthreads();

    const int w = tid >> 5, l = tid & 31;
    if (w < 3) {
        const float* W  = (w == 0) ? Wf : (w == 1) ? Wu : Wo;
        const float* bb = (w == 0) ? bf : (w == 1) ? bu : bo;
        const float* th = (w == 0) ? thf : (w == 1) ? thu : tho;
        for (int qq = 0; qq < NQ; qq++) {
            float s = 0.0f;
            for (int k = l; k < HH; k += 32) s += sx[k] * W[qq * HH + k];
#pragma unroll
            for (int o = 16; o > 0; o >>= 1) s += __shfl_xor_sync(0xffffffffu, s, o);
            if (l == 0) q[w][qq] = cosf(s + bb[qq] + th[qq]);
        }
    }
    __syncthreads();

    if (tid < NQ) {
        float f = 1.0f / (1.0f + expf(-q[0][tid]));
        float g = tanhf(q[1][tid]);
        float o = 1.0f / (1.0f + expf(-q[2][tid]));
        hout[tid] = o * tanhf(f * g);
    }
    __syncthreads();

    if (tid < TTAG) {
        float s = bt[tid];
#pragma unroll
        for (int qq = 0; qq < NQ; qq++) s += hout[qq] * Wt[tid * NQ + qq];
        lg[tid] = s;
    }
    __syncthreads();

    if (tid == 0) {
        float m = lg[0];
        for (int i = 1; i < TTAG; i++) m = fmaxf(m, lg[i]);
        float sum = 0.0f;
        for (int i = 0; i < TTAG; i++) sum += expf(lg[i] - m);
        lse = m + logf(sum);
    }
    __syncthreads();

    if (tid < TTAG) out[(size_t)b * TTAG + tid] = lg[tid] - lse;
}

// ---------------------------------------------------------------------------
extern "C" void kernel_launch(void* const* d_in, const int* in_sizes, int n_in,
                              void* d_out, int out_size)
{
    const float* x   = (const float*)d_in[0];
    const float* Wih = (const float*)d_in[1];
    const float* Whh = (const float*)d_in[2];
    const float* bih = (const float*)d_in[3];
    const float* bhh = (const float*)d_in[4];
    const float* Wf  = (const float*)d_in[5];
    const float* bf  = (const float*)d_in[6];
    // d_in[7]=Wi, d_in[8]=bi: computed-but-unused in reference -> skipped
    const float* Wu  = (const float*)d_in[9];
    const float* bu  = (const float*)d_in[10];
    const float* Wo  = (const float*)d_in[11];
    const float* bo  = (const float*)d_in[12];
    const float* thf = (const float*)d_in[13];
    // d_in[14]=thi unused
    const float* thu = (const float*)d_in[15];
    const float* tho = (const float*)d_in[16];
    const float* Wt  = (const float*)d_in[17];
    const float* bt  = (const float*)d_in[18];
    float* out = (float*)d_out;

    init_kernel<<<64, 256>>>();
    dim3 pg(G4H / 64, SS);                       // (32, 512)
    precompute_kernel<<<pg, 256>>>(x, Wih, bih, bhh);
    for (int t = 0; t < SS; t++) {
        step_kernel<<<128, 256>>>(Whh, t);
    }
    final_kernel<<<BB, 128>>>(Wf, bf, Wu, bu, Wo, bo, thf, thu, tho, Wt, bt, out);
}

// round 2
// speedup vs baseline: 1.7200x; 1.7200x over previous
#include <cuda_runtime.h>
#include <math.h>
#include <stdint.h>

#define BB 128
#define SS 512
#define HH 512
#define NQ 8
#define TTAG 50

typedef unsigned long long u64;

// Scratch
__device__ float g_Xz[(size_t)SS * 4 * HH * BB];   // [t][gate][j][b]
__device__ float g_h2[2][HH * BB];                 // [buf][j][b]
__device__ int            g_cnt[4];
__device__ volatile int   g_gen[4];

__device__ __forceinline__ u64 dup2(float v) {
    u64 d; asm("mov.b64 %0,{%1,%1};" : "=l"(d) : "f"(v)); return d;
}
__device__ __forceinline__ void fma2(u64 &d, u64 a, u64 b) {
    asm("fma.rn.f32x2 %0,%1,%2,%0;" : "+l"(d) : "l"(a), "l"(b));
}
__device__ __forceinline__ float2 unpk(u64 d) {
    float2 r; asm("mov.b64 {%0,%1},%2;" : "=f"(r.x), "=f"(r.y) : "l"(d)); return r;
}
__device__ __forceinline__ float sigf(float x) { return 1.0f / (1.0f + __expf(-x)); }
__device__ __forceinline__ float tanhf_fast(float x) {
    return 1.0f - 2.0f / (__expf(2.0f * x) + 1.0f);
}

// ---------------------------------------------------------------------------
// Precompute: g_Xz[t][g][j][b] = sum_e x[b][t][e]*Wih[g*512+j][e] + bih+bhh
// Tiles: BM=128 (batch), BN=128 (cols), BK=16; 256 threads, 8x8 per thread,
// f32x2 accumulators packed over column pairs.
// ---------------------------------------------------------------------------
__global__ __launch_bounds__(256) void precompute_kernel(
    const float* __restrict__ x, const float* __restrict__ Wih,
    const float* __restrict__ bih, const float* __restrict__ bhh)
{
    __shared__ float As[16][132];   // [k][m]
    __shared__ float Bs[16][136];   // [k][n]  (136*4 = 544B, 16B-aligned rows)

    const int t   = blockIdx.y;
    const int n0  = blockIdx.x * 128;
    const int tid = threadIdx.x;
    const int ty = tid >> 4, tx = tid & 15;
    const int m0 = ty * 8, c0 = tx * 8;

    u64 acc[8][4];
#pragma unroll
    for (int m = 0; m < 8; m++)
#pragma unroll
        for (int cp = 0; cp < 4; cp++) acc[m][cp] = 0ull;

    const int la_b = tid >> 1, la_k = (tid & 1) * 8;
    const float* xrow = x + ((size_t)la_b * SS + t) * HH;
    const int lb_c = tid >> 1, lb_k = (tid & 1) * 8;
    const float* wrow = Wih + (size_t)(n0 + lb_c) * HH;

    for (int kc = 0; kc < HH; kc += 16) {
        float4 a0 = *(const float4*)(xrow + kc + la_k);
        float4 a1 = *(const float4*)(xrow + kc + la_k + 4);
        float4 b0 = *(const float4*)(wrow + kc + lb_k);
        float4 b1 = *(const float4*)(wrow + kc + lb_k + 4);
        As[la_k + 0][la_b] = a0.x; As[la_k + 1][la_b] = a0.y;
        As[la_k + 2][la_b] = a0.z; As[la_k + 3][la_b] = a0.w;
        As[la_k + 4][la_b] = a1.x; As[la_k + 5][la_b] = a1.y;
        As[la_k + 6][la_b] = a1.z; As[la_k + 7][la_b] = a1.w;
        Bs[lb_k + 0][lb_c] = b0.x; Bs[lb_k + 1][lb_c] = b0.y;
        Bs[lb_k + 2][lb_c] = b0.z; Bs[lb_k + 3][lb_c] = b0.w;
        Bs[lb_k + 4][lb_c] = b1.x; Bs[lb_k + 5][lb_c] = b1.y;
        Bs[lb_k + 6][lb_c] = b1.z; Bs[lb_k + 7][lb_c] = b1.w;
        __syncthreads();

#pragma unroll
        for (int k = 0; k < 16; k++) {
            float4 h0 = *(const float4*)&As[k][m0];
            float4 h1 = *(const float4*)&As[k][m0 + 4];
            ulonglong2 wA = *(const ulonglong2*)&Bs[k][c0];
            ulonglong2 wB = *(const ulonglong2*)&Bs[k][c0 + 4];
            u64 w2[4] = {wA.x, wA.y, wB.x, wB.y};
            float av[8] = {h0.x, h0.y, h0.z, h0.w, h1.x, h1.y, h1.z, h1.w};
#pragma unroll
            for (int m = 0; m < 8; m++) {
                u64 ad = dup2(av[m]);
                fma2(acc[m][0], ad, w2[0]);
                fma2(acc[m][1], ad, w2[1]);
                fma2(acc[m][2], ad, w2[2]);
                fma2(acc[m][3], ad, w2[3]);
            }
        }
        __syncthreads();
    }

    // epilogue: bias add, write transposed [t][g][j][b]
    float4 bi0 = *(const float4*)(bih + n0 + c0);
    float4 bi1 = *(const float4*)(bih + n0 + c0 + 4);
    float4 bh0 = *(const float4*)(bhh + n0 + c0);
    float4 bh1 = *(const float4*)(bhh + n0 + c0 + 4);
    float bias[8] = {bi0.x + bh0.x, bi0.y + bh0.y, bi0.z + bh0.z, bi0.w + bh0.w,
                     bi1.x + bh1.x, bi1.y + bh1.y, bi1.z + bh1.z, bi1.w + bh1.w};
    float vals[8][8];
#pragma unroll
    for (int m = 0; m < 8; m++)
#pragma unroll
        for (int cp = 0; cp < 4; cp++) {
            float2 v = unpk(acc[m][cp]);
            vals[m][2 * cp]     = v.x + bias[2 * cp];
            vals[m][2 * cp + 1] = v.y + bias[2 * cp + 1];
        }
#pragma unroll
    for (int cc = 0; cc < 8; cc++) {
        int col = n0 + c0 + cc;
        int g = col >> 9, j = col & 511;
        float* dst = g_Xz + ((((size_t)t * 4 + g) * HH) + j) * BB + m0;
        *(float4*)dst       = make_float4(vals[0][cc], vals[1][cc], vals[2][cc], vals[3][cc]);
        *(float4*)(dst + 4) = make_float4(vals[4][cc], vals[5][cc], vals[6][cc], vals[7][cc]);
    }
}

// ---------------------------------------------------------------------------
// Persistent LSTM recurrence.
// Grid = 128 CTAs = 32 col-groups (16 hidden units x 4 gates) x 4 batch-groups
// (32 rows). Each batch-group of 32 CTAs is a fully independent pipeline with
// its own 32-CTA barrier. Whh slice resident in smem. 8 warps split K (64 k
// each), f32x2 FMAs, smem partial reduction, CTA-local gate fusion, c in smem.
// ---------------------------------------------------------------------------
#define RSM_WS   0                    // [512][68] floats (139264 B)
#define RSM_HS   (512 * 68)           // [512][32] staging / [8][32][64] partials
#define RSM_ZB   (RSM_HS + 512 * 32)  // [64][33] z buffer
#define RSM_CS   (RSM_ZB + 64 * 33)   // [16][32] cell state
#define RSM_TOT  (RSM_CS + 16 * 32)   // floats total = 53824 -> 215296 B

extern __shared__ float smem[];

__device__ __forceinline__ void group_bar(int bg) {
    __threadfence();
    __syncthreads();
    if (threadIdx.x == 0) {
        int g = g_gen[bg];
        if (atomicAdd(&g_cnt[bg], 1) == 31) {
            g_cnt[bg] = 0;
            __threadfence();
            g_gen[bg] = g + 1;
        } else {
            while (g_gen[bg] == g) { __nanosleep(64); }
        }
        __threadfence();
    }
    __syncthreads();
}

__global__ void __launch_bounds__(256, 1) lstm_persistent(const float* __restrict__ Whh)
{
    float* Ws  = smem + RSM_WS;
    float* hsp = smem + RSM_HS;
    float* zb  = smem + RSM_ZB;
    float* cs  = smem + RSM_CS;

    const int tid = threadIdx.x;
    const int cg = blockIdx.x & 31, bg = blockIdx.x >> 5;
    const int j0 = cg * 16, b0 = bg * 32;

    // Load Whh slice once: Ws[k][c], c = gate*16 + jj
    for (int i = tid; i < 64 * 128; i += 256) {
        int c = i & 63;
        int kq = i >> 6;                          // k-quad 0..127
        int gate = c >> 4, jj = c & 15;
        const float* src = Whh + (size_t)(gate * HH + j0 + jj) * HH + kq * 4;
        float4 v = *(const float4*)src;
        float* d = Ws + (kq * 4) * 68 + c;
        d[0 * 68] = v.x; d[1 * 68] = v.y; d[2 * 68] = v.z; d[3 * 68] = v.w;
    }
    // zero cell state and h0 for our batch rows
    for (int i = tid; i < 512; i += 256) cs[i] = 0.0f;
    for (int i = tid; i < 512 * 32; i += 256) {
        int k = i >> 5, bb = i & 31;
        g_h2[0][k * BB + b0 + bb] = 0.0f;
    }
    group_bar(bg);

    const int w = tid >> 5, lane = tid & 31;
    const int ct = lane & 7, bt = lane >> 3;
    const int c0 = ct * 8, bl = bt * 8;
    const int kbase = w * 64;

    for (int t = 0; t < SS; t++) {
        const float* __restrict__ hcur = g_h2[t & 1];
        float* __restrict__ hnxt = g_h2[(t + 1) & 1];

        // stage h[k][b0..b0+31] -> hsp   (bypass L1: written by peer CTAs)
        for (int i = tid; i < 512 * 8; i += 256) {
            int k = i >> 3, seg = (i & 7) * 4;
            float4 v = __ldcg((const float4*)(hcur + (size_t)k * BB + b0 + seg));
            *(float4*)&hsp[k * 32 + seg] = v;
        }
        __syncthreads();

        // split-K GEMM: warp w covers k in [kbase, kbase+64)
        u64 acc[8][4];
#pragma unroll
        for (int b = 0; b < 8; b++)
#pragma unroll
            for (int cp = 0; cp < 4; cp++) acc[b][cp] = 0ull;

#pragma unroll 4
        for (int kk = 0; kk < 64; kk++) {
            int k = kbase + kk;
            float4 h0 = *(const float4*)&hsp[k * 32 + bl];
            float4 h1 = *(const float4*)&hsp[k * 32 + bl + 4];
            ulonglong2 wA = *(const ulonglong2*)&Ws[k * 68 + c0];
            ulonglong2 wB = *(const ulonglong2*)&Ws[k * 68 + c0 + 4];
            u64 w2[4] = {wA.x, wA.y, wB.x, wB.y};
            float hv[8] = {h0.x, h0.y, h0.z, h0.w, h1.x, h1.y, h1.z, h1.w};
#pragma unroll
            for (int b = 0; b < 8; b++) {
                u64 hd = dup2(hv[b]);
                fma2(acc[b][0], hd, w2[0]);
                fma2(acc[b][1], hd, w2[1]);
                fma2(acc[b][2], hd, w2[2]);
                fma2(acc[b][3], hd, w2[3]);
            }
        }
        __syncthreads();           // hs reads done; reuse region as partials

#pragma unroll
        for (int b = 0; b < 8; b++) {
            float* p = hsp + ((size_t)(w * 32) + bl + b) * 64 + c0;
#pragma unroll
            for (int cp = 0; cp < 4; cp++) *(u64*)(p + cp * 2) = acc[b][cp];
        }
        __syncthreads();

        // reduce 8 warp-partials + add Xz, write z to zbuf[c][b]
        {
            int bb = tid & 31;
            int c0r = (tid >> 5) * 8;
            float s[8] = {0, 0, 0, 0, 0, 0, 0, 0};
#pragma unroll
            for (int ww = 0; ww < 8; ww++) {
                const float* p = hsp + ((size_t)(ww * 32) + bb) * 64 + c0r;
                float4 r0 = *(const float4*)p;
                float4 r1 = *(const float4*)(p + 4);
                s[0] += r0.x; s[1] += r0.y; s[2] += r0.z; s[3] += r0.w;
                s[4] += r1.x; s[5] += r1.y; s[6] += r1.z; s[7] += r1.w;
            }
            int g = c0r >> 4, jjb = c0r & 15;
            const float* xz = g_Xz + ((((size_t)t * 4 + g) * HH) + j0 + jjb) * BB + b0 + bb;
#pragma unroll
            for (int i = 0; i < 8; i++) s[i] += xz[(size_t)i * BB];
#pragma unroll
            for (int i = 0; i < 8; i++) zb[(c0r + i) * 33 + bb] = s[i];
        }
        __syncthreads();

        // gate fusion (CTA owns all 4 gates of its 16 j's)
#pragma unroll
        for (int it = 0; it < 2; it++) {
            int idx = tid + it * 256;
            int bb = idx & 31, j = idx >> 5;
            float zi = zb[(j)*33 + bb];
            float zf = zb[(16 + j) * 33 + bb];
            float zg = zb[(32 + j) * 33 + bb];
            float zo = zb[(48 + j) * 33 + bb];
            float cold = cs[j * 32 + bb];
            float cn = sigf(zf) * cold + sigf(zi) * tanhf_fast(zg);
            cs[j * 32 + bb] = cn;
            hnxt[(size_t)(j0 + j) * BB + b0 + bb] = sigf(zo) * tanhf_fast(cn);
        }
        group_bar(bg);
    }
}

// ---------------------------------------------------------------------------
// Quantum head + log_softmax (final h in g_h2[0], layout [j][b])
// ---------------------------------------------------------------------------
__global__ __launch_bounds__(128) void final_kernel(
    const float* __restrict__ Wf, const float* __restrict__ bf,
    const float* __restrict__ Wu, const float* __restrict__ bu,
    const float* __restrict__ Wo, const float* __restrict__ bo,
    const float* __restrict__ thf, const float* __restrict__ thu,
    const float* __restrict__ tho,
    const float* __restrict__ Wt, const float* __restrict__ bt,
    float* __restrict__ out)
{
    __shared__ float sx[HH];
    __shared__ float q[3][NQ];
    __shared__ float hout[NQ];
    __shared__ float lg[TTAG];
    __shared__ float lse;

    const int b = blockIdx.x;
    const int tid = threadIdx.x;

    for (int k = tid; k < HH; k += 128) sx[k] = g_h2[0][(size_t)k * BB + b];
    __syncthreads();

    const int w = tid >> 5, l = tid & 31;
    if (w < 3) {
        const float* W  = (w == 0) ? Wf : (w == 1) ? Wu : Wo;
        const float* bbv = (w == 0) ? bf : (w == 1) ? bu : bo;
        const float* th = (w == 0) ? thf : (w == 1) ? thu : tho;
        for (int qq = 0; qq < NQ; qq++) {
            float s = 0.0f;
            for (int k = l; k < HH; k += 32) s += sx[k] * W[qq * HH + k];
#pragma unroll
            for (int o = 16; o > 0; o >>= 1) s += __shfl_xor_sync(0xffffffffu, s, o);
            if (l == 0) q[w][qq] = cosf(s + bbv[qq] + th[qq]);
        }
    }
    __syncthreads();

    if (tid < NQ) {
        float f = 1.0f / (1.0f + expf(-q[0][tid]));
        float g = tanhf(q[1][tid]);
        float o = 1.0f / (1.0f + expf(-q[2][tid]));
        hout[tid] = o * tanhf(f * g);
    }
    __syncthreads();

    if (tid < TTAG) {
        float s = bt[tid];
#pragma unroll
        for (int qq = 0; qq < NQ; qq++) s += hout[qq] * Wt[tid * NQ + qq];
        lg[tid] = s;
    }
    __syncthreads();

    if (tid == 0) {
        float m = lg[0];
        for (int i = 1; i < TTAG; i++) m = fmaxf(m, lg[i]);
        float sum = 0.0f;
        for (int i = 0; i < TTAG; i++) sum += expf(lg[i] - m);
        lse = m + logf(sum);
    }
    __syncthreads();

    if (tid < TTAG) out[(size_t)b * TTAG + tid] = lg[tid] - lse;
}

// ---------------------------------------------------------------------------
extern "C" void kernel_launch(void* const* d_in, const int* in_sizes, int n_in,
                              void* d_out, int out_size)
{
    const float* x   = (const float*)d_in[0];
    const float* Wih = (const float*)d_in[1];
    const float* Whh = (const float*)d_in[2];
    const float* bih = (const float*)d_in[3];
    const float* bhh = (const float*)d_in[4];
    const float* Wf  = (const float*)d_in[5];
    const float* bf  = (const float*)d_in[6];
    const float* Wu  = (const float*)d_in[9];
    const float* bu  = (const float*)d_in[10];
    const float* Wo  = (const float*)d_in[11];
    const float* bo  = (const float*)d_in[12];
    const float* thf = (const float*)d_in[13];
    const float* thu = (const float*)d_in[15];
    const float* tho = (const float*)d_in[16];
    const float* Wt  = (const float*)d_in[17];
    const float* bt  = (const float*)d_in[18];
    float* out = (float*)d_out;

    cudaFuncSetAttribute(lstm_persistent,
                         cudaFuncAttributeMaxDynamicSharedMemorySize, RSM_TOT * 4);

    dim3 pg(16, SS);    // (2048/128 col-blocks, 512 timesteps)
    precompute_kernel<<<pg, 256>>>(x, Wih, bih, bhh);
    lstm_persistent<<<128, 256, RSM_TOT * 4>>>(Whh);
    final_kernel<<<BB, 128>>>(Wf, bf, Wu, bu, Wo, bo, thf, thu, tho, Wt, bt, out);
}